// round 4
// baseline (speedup 1.0000x reference)
#include <cuda_runtime.h>
#include <cuda_bf16.h>
#include <cstdint>

// Problem constants (match reference)
#define NMAX      50000
#define EMAX      800000
#define IN_DIM    256
#define H_DIM     128
#define OUT_DIM   64
#define K_STEPS   10
#define ALPHA_F   0.1f

// -------- scratch (no allocation allowed -> device globals) --------
__device__ float gX0[(size_t)NMAX * OUT_DIM];  // X @ (W1@W2)
__device__ float gP [(size_t)NMAX * OUT_DIM];  // prop(X0) + c
__device__ float gH [(size_t)NMAX * OUT_DIM];  // h = prop(P) + b2
__device__ float gA [(size_t)NMAX * OUT_DIM];  // ping
__device__ float gB [(size_t)NMAX * OUT_DIM];  // pong
__device__ float gWc[IN_DIM * OUT_DIM];        // W1 @ W2  (256x64)
__device__ float gC [OUT_DIM];                 // b1 @ W2
__device__ int   gIdxIs64;
// CSR scratch
__device__ int   gCount[NMAX];
__device__ int   gRowPtr[NMAX + 1];
__device__ int   gWp[NMAX];
__device__ int2  gCsr[EMAX];                   // (src, w-bits) sorted by dst

// ------------- dtype detection: int64 vs int32 edge_index -------------
__global__ void detect_idx_dtype(const void* __restrict__ ei, int N)
{
    const long long* p = (const long long*)ei;
    int ok = 1;
    for (int i = 0; i < 64; i++) {
        long long v = p[i];
        if (v < 0 || v >= N) { ok = 0; break; }
    }
    gIdxIs64 = ok;
}

// ------------- CSR build -------------
__global__ void hist_dst(const void* __restrict__ ei, int E)
{
    int e = blockIdx.x * blockDim.x + threadIdx.x;
    if (e >= E) return;
    int d;
    if (gIdxIs64) d = (int)((const long long*)ei)[E + e];
    else          d = ((const int*)ei)[E + e];
    atomicAdd(&gCount[d], 1);
}

__global__ void scan_rowptr(int N, int E)
{
    __shared__ int sSum[1024];
    const int tid = threadIdx.x;
    const int chunk = (N + 1023) / 1024;
    const int lo = tid * chunk;
    const int hi = min(lo + chunk, N);

    int s = 0;
    for (int i = lo; i < hi; i++) s += gCount[i];
    sSum[tid] = s;
    __syncthreads();

    for (int off = 1; off < 1024; off <<= 1) {
        int v = (tid >= off) ? sSum[tid - off] : 0;
        __syncthreads();
        sSum[tid] += v;
        __syncthreads();
    }
    int run = (tid == 0) ? 0 : sSum[tid - 1];
    for (int i = lo; i < hi; i++) {
        gRowPtr[i] = run;
        gWp[i]     = run;
        run += gCount[i];
    }
    if (tid == 1023) gRowPtr[N] = E;
}

__global__ void fill_csr(const void* __restrict__ ei, const float* __restrict__ ew, int E)
{
    int e = blockIdx.x * blockDim.x + threadIdx.x;
    if (e >= E) return;
    int s, d;
    if (gIdxIs64) {
        const long long* p = (const long long*)ei;
        s = (int)p[e];
        d = (int)p[E + e];
    } else {
        const int* p = (const int*)ei;
        s = p[e];
        d = p[E + e];
    }
    int pos = atomicAdd(&gWp[d], 1);
    gCsr[pos] = make_int2(s, __float_as_int(ew[e]));
}

// ------------- tiny: Wc = W1 @ W2 (256x64), c = b1 @ W2 (64) -------------
__global__ void combine_weights(const float* __restrict__ W1,
                                const float* __restrict__ b1,
                                const float* __restrict__ W2)
{
    int idx = blockIdx.x * blockDim.x + threadIdx.x;
    if (idx < IN_DIM * OUT_DIM) {
        int i = idx >> 6, j = idx & 63;
        float s = 0.0f;
        const float* w1r = W1 + (size_t)i * H_DIM;
#pragma unroll 8
        for (int k = 0; k < H_DIM; k++)
            s += w1r[k] * W2[(size_t)k * OUT_DIM + j];
        gWc[idx] = s;
    } else if (idx < IN_DIM * OUT_DIM + OUT_DIM) {
        int j = idx - IN_DIM * OUT_DIM;
        float s = 0.0f;
#pragma unroll 8
        for (int k = 0; k < H_DIM; k++)
            s += b1[k] * W2[(size_t)k * OUT_DIM + j];
        gC[j] = s;
    }
}

// ---------------- SGEMM: C[M,N] = A @ B ----------------
template<int BM, int BN, int BK, int TM, int TN>
__global__ void sgemm(int M, int N, int K,
                      const float* __restrict__ A,
                      const float* __restrict__ B,
                      float* __restrict__ C)
{
    constexpr int THREADS = (BM / TM) * (BN / TN);
    __shared__ float As[BK][BM];
    __shared__ float Bs[BK][BN];

    const int tid = threadIdx.x;
    const int tc  = tid % (BN / TN);
    const int tr  = tid / (BN / TN);
    const int rowBase = blockIdx.x * BM;
    const int colBase = blockIdx.y * BN;

    float acc[TM][TN];
#pragma unroll
    for (int i = 0; i < TM; i++)
#pragma unroll
        for (int j = 0; j < TN; j++) acc[i][j] = 0.0f;

    constexpr int A_VECS = BM * BK / (THREADS * 4);
    constexpr int B_VECS = BK * BN / (THREADS * 4);

    for (int k0 = 0; k0 < K; k0 += BK) {
#pragma unroll
        for (int i = 0; i < A_VECS; i++) {
            int lin = (tid + i * THREADS) * 4;
            int r = lin / BK, c = lin % BK;
            int grow = rowBase + r;
            float4 v = make_float4(0.f, 0.f, 0.f, 0.f);
            if (grow < M)
                v = *reinterpret_cast<const float4*>(A + (size_t)grow * K + k0 + c);
            As[c + 0][r] = v.x;
            As[c + 1][r] = v.y;
            As[c + 2][r] = v.z;
            As[c + 3][r] = v.w;
        }
#pragma unroll
        for (int i = 0; i < B_VECS; i++) {
            int lin = (tid + i * THREADS) * 4;
            int r = lin / BN, c = lin % BN;
            *reinterpret_cast<float4*>(&Bs[r][c]) =
                *reinterpret_cast<const float4*>(B + (size_t)(k0 + r) * N + colBase + c);
        }
        __syncthreads();

#pragma unroll
        for (int k = 0; k < BK; k++) {
            float ra[TM], rb[TN];
#pragma unroll
            for (int i = 0; i < TM; i++) ra[i] = As[k][tr * TM + i];
#pragma unroll
            for (int j = 0; j < TN; j++) rb[j] = Bs[k][tc * TN + j];
#pragma unroll
            for (int i = 0; i < TM; i++)
#pragma unroll
                for (int j = 0; j < TN; j++) acc[i][j] += ra[i] * rb[j];
        }
        __syncthreads();
    }

#pragma unroll
    for (int i = 0; i < TM; i++) {
        int grow = rowBase + tr * TM + i;
        if (grow >= M) continue;
#pragma unroll
        for (int j = 0; j < TN; j += 4) {
            float4 v = make_float4(acc[i][j], acc[i][j + 1], acc[i][j + 2], acc[i][j + 3]);
            *reinterpret_cast<float4*>(C + (size_t)grow * N + colBase + tc * TN + j) = v;
        }
    }
}

// ------------- CSR gather prop, DIM=64, float4 lanes -------------
// out[n,:] = wscale * sum_{e in in(n)} w_e * x[src_e,:]  (+ ascale*addv[n,:]) (+ bias[:])
// One warp per node. Half-warps process alternate edges; lanes 0-15 / 16-31
// each cover the full 64-float row as 16 float4s. Combine via shfl, write float4.
__global__ void gather64(const float4* __restrict__ x4,
                         float4* __restrict__ out4,
                         const float4* __restrict__ addv4,  // may be null
                         const float4* __restrict__ bias4,  // may be null
                         int N, float wscale, float ascale)
{
    int warp = (blockIdx.x * blockDim.x + threadIdx.x) >> 5;
    int lane = threadIdx.x & 31;
    if (warp >= N) return;

    const int beg  = gRowPtr[warp];
    const int end  = gRowPtr[warp + 1];
    const int half = lane >> 4;
    const int q    = lane & 15;

    float4 acc = make_float4(0.f, 0.f, 0.f, 0.f);

    int e = beg + half;
    for (; e + 2 < end; e += 4) {
        int2 s0 = __ldg(&gCsr[e]);
        int2 s1 = __ldg(&gCsr[e + 2]);
        float4 v0 = __ldg(x4 + (size_t)s0.x * 16 + q);
        float4 v1 = __ldg(x4 + (size_t)s1.x * 16 + q);
        float w0 = __int_as_float(s0.y);
        float w1 = __int_as_float(s1.y);
        acc.x += w0 * v0.x + w1 * v1.x;
        acc.y += w0 * v0.y + w1 * v1.y;
        acc.z += w0 * v0.z + w1 * v1.z;
        acc.w += w0 * v0.w + w1 * v1.w;
    }
    if (e < end) {
        int2 s0 = __ldg(&gCsr[e]);
        float4 v0 = __ldg(x4 + (size_t)s0.x * 16 + q);
        float w0 = __int_as_float(s0.y);
        acc.x += w0 * v0.x;
        acc.y += w0 * v0.y;
        acc.z += w0 * v0.z;
        acc.w += w0 * v0.w;
    }

    // fold upper half into lower half
    acc.x += __shfl_down_sync(0xffffffffu, acc.x, 16);
    acc.y += __shfl_down_sync(0xffffffffu, acc.y, 16);
    acc.z += __shfl_down_sync(0xffffffffu, acc.z, 16);
    acc.w += __shfl_down_sync(0xffffffffu, acc.w, 16);

    if (half == 0) {
        float4 r;
        r.x = wscale * acc.x;
        r.y = wscale * acc.y;
        r.z = wscale * acc.z;
        r.w = wscale * acc.w;
        if (addv4) {
            float4 a = __ldg(addv4 + (size_t)warp * 16 + q);
            r.x += ascale * a.x; r.y += ascale * a.y;
            r.z += ascale * a.z; r.w += ascale * a.w;
        }
        if (bias4) {
            float4 b = __ldg(bias4 + q);
            r.x += b.x; r.y += b.y; r.z += b.z; r.w += b.w;
        }
        out4[(size_t)warp * 16 + q] = r;
    }
}

__global__ void fill_tail(float* __restrict__ out, int start, int total)
{
    int i = start + blockIdx.x * blockDim.x + threadIdx.x;
    if (i < total) out[i] = 10.0f;
}

extern "C" void kernel_launch(void* const* d_in, const int* in_sizes, int n_in,
                              void* d_out, int out_size)
{
    const float* features = (const float*)d_in[0];
    const void*  ei       = d_in[1];
    const float* ew       = (const float*)d_in[2];
    const float* W1       = (const float*)d_in[3];
    const float* b1       = (const float*)d_in[4];
    const float* W2       = (const float*)d_in[5];
    const float* b2       = (const float*)d_in[6];
    float*       out      = (float*)d_out;

    const int N = in_sizes[0] / IN_DIM;
    const int E = in_sizes[2];

    float *X0, *P, *H, *A, *B, *Wc, *C;
    cudaGetSymbolAddress((void**)&X0, gX0);
    cudaGetSymbolAddress((void**)&P,  gP);
    cudaGetSymbolAddress((void**)&H,  gH);
    cudaGetSymbolAddress((void**)&A,  gA);
    cudaGetSymbolAddress((void**)&B,  gB);
    cudaGetSymbolAddress((void**)&Wc, gWc);
    cudaGetSymbolAddress((void**)&C,  gC);
    int* countPtr;
    cudaGetSymbolAddress((void**)&countPtr, gCount);

    // ---- CSR build ----
    detect_idx_dtype<<<1, 1>>>(ei, N);
    cudaMemsetAsync(countPtr, 0, (size_t)N * sizeof(int));
    hist_dst<<<(E + 255) / 256, 256>>>(ei, E);
    scan_rowptr<<<1, 1024>>>(N, E);
    fill_csr<<<(E + 255) / 256, 256>>>(ei, ew, E);

    // ---- combined weights: Wc = W1@W2, c = b1@W2 ----
    {
        int tot = IN_DIM * OUT_DIM + OUT_DIM;
        combine_weights<<<(tot + 255) / 256, 256>>>(W1, b1, W2);
    }

    // ---- X0 = features @ Wc  (50000x256 @ 256x64) ----
    {
        dim3 grid((N + 127) / 128, 1);
        sgemm<128, 64, 16, 8, 8><<<grid, 128>>>(N, OUT_DIM, IN_DIM, features, Wc, X0);
    }

    const int gthreads = 256;
    const int wpb = gthreads / 32;
    const int gblocks = (N + wpb - 1) / wpb;

    // P = prop(X0) + c
    gather64<<<gblocks, gthreads>>>((const float4*)X0, (float4*)P, nullptr,
                                    (const float4*)C, N, 1.0f, 0.0f);
    // H = prop(P) + b2
    gather64<<<gblocks, gthreads>>>((const float4*)P, (float4*)H, nullptr,
                                    (const float4*)b2, N, 1.0f, 0.0f);

    // ---- APPNP: x_{k+1} = (1-a)*prop(x_k) + a*h ----
    const float* xcur = H;
    for (int k = 0; k < K_STEPS; k++) {
        float* xnext = (k == K_STEPS - 1) ? out : ((k & 1) ? B : A);
        gather64<<<gblocks, gthreads>>>((const float4*)xcur, (float4*)xnext,
                                        (const float4*)H, nullptr,
                                        N, 1.0f - ALPHA_F, ALPHA_F);
        xcur = xnext;
    }

    // tail (reference returns (x, 10); fill any extra outputs with 10)
    int tail = out_size - N * OUT_DIM;
    if (tail > 0)
        fill_tail<<<(tail + 255) / 256, 256>>>(out, N * OUT_DIM, out_size);
}

// round 5
// speedup vs baseline: 1.5063x; 1.5063x over previous
#include <cuda_runtime.h>
#include <cuda_bf16.h>
#include <cstdint>

// Problem constants (match reference)
#define NMAX      50000
#define EMAX      800000
#define IN_DIM    256
#define H_DIM     128
#define OUT_DIM   64
#define K_STEPS   10
#define ALPHA_F   0.1f

// -------- scratch (no allocation allowed -> device globals) --------
__device__ float gX0[(size_t)NMAX * OUT_DIM];  // X @ (W1@W2)
__device__ float gP [(size_t)NMAX * OUT_DIM];  // prop(X0) + c
__device__ float gH [(size_t)NMAX * OUT_DIM];  // h = prop(P) + b2
__device__ float gA [(size_t)NMAX * OUT_DIM];  // ping
__device__ float gB [(size_t)NMAX * OUT_DIM];  // pong
__device__ float gWc[IN_DIM * OUT_DIM];        // W1 @ W2  (256x64)
__device__ float gC [OUT_DIM];                 // b1 @ W2
__device__ int   gIdxIs64;
// CSR scratch
__device__ int   gCount[NMAX];
__device__ int   gRowPtr[NMAX + 1];
__device__ int   gWp[NMAX];
__device__ int2  gCsr[EMAX];                   // (src, w-bits) sorted by dst

// ------------- dtype detection: int64 vs int32 edge_index -------------
__global__ void detect_idx_dtype(const void* __restrict__ ei, int N)
{
    const long long* p = (const long long*)ei;
    int ok = 1;
    for (int i = 0; i < 64; i++) {
        long long v = p[i];
        if (v < 0 || v >= N) { ok = 0; break; }
    }
    gIdxIs64 = ok;
}

// ------------- CSR build -------------
__global__ void hist_dst(const void* __restrict__ ei, int E)
{
    int e = blockIdx.x * blockDim.x + threadIdx.x;
    if (e >= E) return;
    int d;
    if (gIdxIs64) d = (int)((const long long*)ei)[E + e];
    else          d = ((const int*)ei)[E + e];
    atomicAdd(&gCount[d], 1);
}

__global__ void scan_rowptr(int N, int E)
{
    __shared__ int sSum[1024];
    const int tid = threadIdx.x;
    const int chunk = (N + 1023) / 1024;
    const int lo = tid * chunk;
    const int hi = min(lo + chunk, N);

    int s = 0;
    for (int i = lo; i < hi; i++) s += gCount[i];
    sSum[tid] = s;
    __syncthreads();

    for (int off = 1; off < 1024; off <<= 1) {
        int v = (tid >= off) ? sSum[tid - off] : 0;
        __syncthreads();
        sSum[tid] += v;
        __syncthreads();
    }
    int run = (tid == 0) ? 0 : sSum[tid - 1];
    for (int i = lo; i < hi; i++) {
        gRowPtr[i] = run;
        gWp[i]     = run;
        run += gCount[i];
    }
    if (tid == 1023) gRowPtr[N] = E;
}

// two edges per thread for a bit of MLP
__global__ void fill_csr(const void* __restrict__ ei, const float* __restrict__ ew, int E)
{
    int t = blockIdx.x * blockDim.x + threadIdx.x;
#pragma unroll
    for (int u = 0; u < 2; u++) {
        int e = t * 2 + u;
        if (e >= E) return;
        int s, d;
        if (gIdxIs64) {
            const long long* p = (const long long*)ei;
            s = (int)p[e];
            d = (int)p[E + e];
        } else {
            const int* p = (const int*)ei;
            s = p[e];
            d = p[E + e];
        }
        int pos = atomicAdd(&gWp[d], 1);
        gCsr[pos] = make_int2(s, __float_as_int(ew[e]));
    }
}

// ------------- tiny: Wc = W1 @ W2 (256x64), c = b1 @ W2 (64) -------------
__global__ void combine_weights(const float* __restrict__ W1,
                                const float* __restrict__ b1,
                                const float* __restrict__ W2)
{
    int idx = blockIdx.x * blockDim.x + threadIdx.x;
    if (idx < IN_DIM * OUT_DIM) {
        int i = idx >> 6, j = idx & 63;
        float s = 0.0f;
        const float* w1r = W1 + (size_t)i * H_DIM;
#pragma unroll 8
        for (int k = 0; k < H_DIM; k++)
            s += w1r[k] * W2[(size_t)k * OUT_DIM + j];
        gWc[idx] = s;
    } else if (idx < IN_DIM * OUT_DIM + OUT_DIM) {
        int j = idx - IN_DIM * OUT_DIM;
        float s = 0.0f;
#pragma unroll 8
        for (int k = 0; k < H_DIM; k++)
            s += b1[k] * W2[(size_t)k * OUT_DIM + j];
        gC[j] = s;
    }
}

// ---------------- SGEMM: C[M,N] = A @ B ----------------
template<int BM, int BN, int BK, int TM, int TN>
__global__ void sgemm(int M, int N, int K,
                      const float* __restrict__ A,
                      const float* __restrict__ B,
                      float* __restrict__ C)
{
    constexpr int THREADS = (BM / TM) * (BN / TN);
    __shared__ float As[BK][BM];
    __shared__ float Bs[BK][BN];

    const int tid = threadIdx.x;
    const int tc  = tid % (BN / TN);
    const int tr  = tid / (BN / TN);
    const int rowBase = blockIdx.x * BM;
    const int colBase = blockIdx.y * BN;

    float acc[TM][TN];
#pragma unroll
    for (int i = 0; i < TM; i++)
#pragma unroll
        for (int j = 0; j < TN; j++) acc[i][j] = 0.0f;

    constexpr int A_VECS = BM * BK / (THREADS * 4);
    constexpr int B_VECS = BK * BN / (THREADS * 4);

    for (int k0 = 0; k0 < K; k0 += BK) {
#pragma unroll
        for (int i = 0; i < A_VECS; i++) {
            int lin = (tid + i * THREADS) * 4;
            int r = lin / BK, c = lin % BK;
            int grow = rowBase + r;
            float4 v = make_float4(0.f, 0.f, 0.f, 0.f);
            if (grow < M)
                v = *reinterpret_cast<const float4*>(A + (size_t)grow * K + k0 + c);
            As[c + 0][r] = v.x;
            As[c + 1][r] = v.y;
            As[c + 2][r] = v.z;
            As[c + 3][r] = v.w;
        }
#pragma unroll
        for (int i = 0; i < B_VECS; i++) {
            int lin = (tid + i * THREADS) * 4;
            int r = lin / BN, c = lin % BN;
            *reinterpret_cast<float4*>(&Bs[r][c]) =
                *reinterpret_cast<const float4*>(B + (size_t)(k0 + r) * N + colBase + c);
        }
        __syncthreads();

#pragma unroll
        for (int k = 0; k < BK; k++) {
            float ra[TM], rb[TN];
#pragma unroll
            for (int i = 0; i < TM; i++) ra[i] = As[k][tr * TM + i];
#pragma unroll
            for (int j = 0; j < TN; j++) rb[j] = Bs[k][tc * TN + j];
#pragma unroll
            for (int i = 0; i < TM; i++)
#pragma unroll
                for (int j = 0; j < TN; j++) acc[i][j] += ra[i] * rb[j];
        }
        __syncthreads();
    }

#pragma unroll
    for (int i = 0; i < TM; i++) {
        int grow = rowBase + tr * TM + i;
        if (grow >= M) continue;
#pragma unroll
        for (int j = 0; j < TN; j += 4) {
            float4 v = make_float4(acc[i][j], acc[i][j + 1], acc[i][j + 2], acc[i][j + 3]);
            *reinterpret_cast<float4*>(C + (size_t)grow * N + colBase + tc * TN + j) = v;
        }
    }
}

// ------------- CSR gather prop (R3-proven form) -------------
// out[n,:] = wscale * sum_{e in in(n)} w_e * x[src_e,:]  (+ ascale*addv[n,:]) (+ bias[:])
// One warp per node; lane l owns columns {l, l+32}.
template<int DIM>
__global__ void gather_prop(const float* __restrict__ x,
                            float* __restrict__ out,
                            const float* __restrict__ addv,  // may be null
                            const float* __restrict__ bias,  // may be null
                            int N, float wscale, float ascale)
{
    constexpr int R = DIM / 32;
    int warp = (blockIdx.x * blockDim.x + threadIdx.x) >> 5;
    int lane = threadIdx.x & 31;
    if (warp >= N) return;

    int e   = gRowPtr[warp];
    int end = gRowPtr[warp + 1];

    float acc[R];
#pragma unroll
    for (int j = 0; j < R; j++) acc[j] = 0.0f;

    for (; e + 1 < end; e += 2) {
        int2 sw0 = __ldg(&gCsr[e]);
        int2 sw1 = __ldg(&gCsr[e + 1]);
        float w0 = __int_as_float(sw0.y);
        float w1 = __int_as_float(sw1.y);
        const float* r0 = x + (size_t)sw0.x * DIM + lane;
        const float* r1 = x + (size_t)sw1.x * DIM + lane;
#pragma unroll
        for (int j = 0; j < R; j++) {
            float v0 = __ldg(r0 + 32 * j);
            float v1 = __ldg(r1 + 32 * j);
            acc[j] += w0 * v0;
            acc[j] += w1 * v1;
        }
    }
    if (e < end) {
        int2 sw = __ldg(&gCsr[e]);
        float w = __int_as_float(sw.y);
        const float* r = x + (size_t)sw.x * DIM + lane;
#pragma unroll
        for (int j = 0; j < R; j++) acc[j] += w * __ldg(r + 32 * j);
    }

    float* o = out + (size_t)warp * DIM + lane;
#pragma unroll
    for (int j = 0; j < R; j++) {
        float v = wscale * acc[j];
        if (addv) v += ascale * addv[(size_t)warp * DIM + lane + 32 * j];
        if (bias) v += bias[lane + 32 * j];
        o[32 * j] = v;
    }
}

__global__ void fill_tail(float* __restrict__ out, int start, int total)
{
    int i = start + blockIdx.x * blockDim.x + threadIdx.x;
    if (i < total) out[i] = 10.0f;
}

extern "C" void kernel_launch(void* const* d_in, const int* in_sizes, int n_in,
                              void* d_out, int out_size)
{
    const float* features = (const float*)d_in[0];
    const void*  ei       = d_in[1];
    const float* ew       = (const float*)d_in[2];
    const float* W1       = (const float*)d_in[3];
    const float* b1       = (const float*)d_in[4];
    const float* W2       = (const float*)d_in[5];
    const float* b2       = (const float*)d_in[6];
    float*       out      = (float*)d_out;

    const int N = in_sizes[0] / IN_DIM;
    const int E = in_sizes[2];

    float *X0, *P, *H, *A, *B, *Wc, *C;
    cudaGetSymbolAddress((void**)&X0, gX0);
    cudaGetSymbolAddress((void**)&P,  gP);
    cudaGetSymbolAddress((void**)&H,  gH);
    cudaGetSymbolAddress((void**)&A,  gA);
    cudaGetSymbolAddress((void**)&B,  gB);
    cudaGetSymbolAddress((void**)&Wc, gWc);
    cudaGetSymbolAddress((void**)&C,  gC);
    int* countPtr;
    cudaGetSymbolAddress((void**)&countPtr, gCount);

    // ---- CSR build ----
    detect_idx_dtype<<<1, 1>>>(ei, N);
    cudaMemsetAsync(countPtr, 0, (size_t)N * sizeof(int));
    hist_dst<<<(E + 255) / 256, 256>>>(ei, E);
    scan_rowptr<<<1, 1024>>>(N, E);
    fill_csr<<<((E + 1) / 2 + 255) / 256, 256>>>(ei, ew, E);

    // ---- combined weights: Wc = W1@W2, c = b1@W2 ----
    {
        int tot = IN_DIM * OUT_DIM + OUT_DIM;
        combine_weights<<<(tot + 255) / 256, 256>>>(W1, b1, W2);
    }

    // ---- X0 = features @ Wc  (50000x256 @ 256x64), proven config ----
    {
        dim3 grid((N + 127) / 128, 1);
        sgemm<128, 64, 16, 8, 4><<<grid, 256>>>(N, OUT_DIM, IN_DIM, features, Wc, X0);
    }

    const int gthreads = 256;
    const int wpb = gthreads / 32;
    const int gblocks = (N + wpb - 1) / wpb;

    // P = prop(X0) + c
    gather_prop<OUT_DIM><<<gblocks, gthreads>>>(X0, P, nullptr, C, N, 1.0f, 0.0f);
    // H = prop(P) + b2
    gather_prop<OUT_DIM><<<gblocks, gthreads>>>(P, H, nullptr, b2, N, 1.0f, 0.0f);

    // ---- APPNP: x_{k+1} = (1-a)*prop(x_k) + a*h ----
    const float* xcur = H;
    for (int k = 0; k < K_STEPS; k++) {
        float* xnext = (k == K_STEPS - 1) ? out : ((k & 1) ? B : A);
        gather_prop<OUT_DIM><<<gblocks, gthreads>>>(xcur, xnext, H, nullptr,
                                                    N, 1.0f - ALPHA_F, ALPHA_F);
        xcur = xnext;
    }

    // tail (reference returns (x, 10); fill any extra outputs with 10)
    int tail = out_size - N * OUT_DIM;
    if (tail > 0)
        fill_tail<<<(tail + 255) / 256, 256>>>(out, N * OUT_DIM, out_size);
}

// round 7
// speedup vs baseline: 1.8894x; 1.2544x over previous
#include <cuda_runtime.h>
#include <cuda_fp16.h>
#include <cstdint>

// Problem constants (match reference)
#define NMAX      50000
#define EMAX      800000
#define IN_DIM    256
#define H_DIM     128
#define OUT_DIM   64
#define K_STEPS   10
#define ALPHA_F   0.1f

// Scale schedule: every prop divides stored values by 4 (exact, folded into
// fp32 scale constants). x_k true = y_k * (16 * 4^k); H true = Hs * 16.
#define PSCALE    4.0f

// -------- scratch (no allocation allowed -> device globals) --------
__device__ __half gX0[(size_t)NMAX * OUT_DIM];  // X @ (W1@W2)          (scale 1)
__device__ __half gP [(size_t)NMAX * OUT_DIM];  // (prop(X0)+c)/4       (scale 4)
__device__ __half gH [(size_t)NMAX * OUT_DIM];  // (prop(P)+b2)/16      (scale 16)
__device__ __half gA [(size_t)NMAX * OUT_DIM];  // ping  (scale 16*4^k)
__device__ __half gB [(size_t)NMAX * OUT_DIM];  // pong
__device__ float  gWc[IN_DIM * OUT_DIM];        // W1 @ W2  (256x64)
__device__ float  gC [OUT_DIM];                 // b1 @ W2
__device__ int    gIdxIs64;
// CSR scratch
__device__ int    gCount[NMAX];
__device__ int    gRowPtr[NMAX + 1];
__device__ int    gWp[NMAX];
__device__ int2   gCsr[EMAX];                   // (src, w-bits) sorted by dst

// ------------- dtype detection: int64 vs int32 edge_index -------------
__global__ void detect_idx_dtype(const void* __restrict__ ei, int N)
{
    const long long* p = (const long long*)ei;
    int ok = 1;
    for (int i = 0; i < 64; i++) {
        long long v = p[i];
        if (v < 0 || v >= N) { ok = 0; break; }
    }
    gIdxIs64 = ok;
}

// ------------- CSR build -------------
__global__ void hist_dst(const void* __restrict__ ei, int E)
{
    int e = blockIdx.x * blockDim.x + threadIdx.x;
    if (e >= E) return;
    int d;
    if (gIdxIs64) d = (int)((const long long*)ei)[E + e];
    else          d = ((const int*)ei)[E + e];
    atomicAdd(&gCount[d], 1);
}

__global__ void scan_rowptr(int N, int E)
{
    __shared__ int sSum[1024];
    const int tid = threadIdx.x;
    const int chunk = (N + 1023) / 1024;
    const int lo = tid * chunk;
    const int hi = min(lo + chunk, N);

    int s = 0;
    for (int i = lo; i < hi; i++) s += gCount[i];
    sSum[tid] = s;
    __syncthreads();

    for (int off = 1; off < 1024; off <<= 1) {
        int v = (tid >= off) ? sSum[tid - off] : 0;
        __syncthreads();
        sSum[tid] += v;
        __syncthreads();
    }
    int run = (tid == 0) ? 0 : sSum[tid - 1];
    for (int i = lo; i < hi; i++) {
        gRowPtr[i] = run;
        gWp[i]     = run;
        run += gCount[i];
    }
    if (tid == 1023) gRowPtr[N] = E;
}

__global__ void fill_csr(const void* __restrict__ ei, const float* __restrict__ ew, int E)
{
    int t = blockIdx.x * blockDim.x + threadIdx.x;
#pragma unroll
    for (int u = 0; u < 2; u++) {
        int e = t * 2 + u;
        if (e >= E) return;
        int s, d;
        if (gIdxIs64) {
            const long long* p = (const long long*)ei;
            s = (int)p[e];
            d = (int)p[E + e];
        } else {
            const int* p = (const int*)ei;
            s = p[e];
            d = p[E + e];
        }
        int pos = atomicAdd(&gWp[d], 1);
        gCsr[pos] = make_int2(s, __float_as_int(ew[e]));
    }
}

// ------------- tiny: Wc = W1 @ W2 (256x64), c = b1 @ W2 (64) -------------
__global__ void combine_weights(const float* __restrict__ W1,
                                const float* __restrict__ b1,
                                const float* __restrict__ W2)
{
    int idx = blockIdx.x * blockDim.x + threadIdx.x;
    if (idx < IN_DIM * OUT_DIM) {
        int i = idx >> 6, j = idx & 63;
        float s = 0.0f;
        const float* w1r = W1 + (size_t)i * H_DIM;
#pragma unroll 8
        for (int k = 0; k < H_DIM; k++)
            s += w1r[k] * W2[(size_t)k * OUT_DIM + j];
        gWc[idx] = s;
    } else if (idx < IN_DIM * OUT_DIM + OUT_DIM) {
        int j = idx - IN_DIM * OUT_DIM;
        float s = 0.0f;
#pragma unroll 8
        for (int k = 0; k < H_DIM; k++)
            s += b1[k] * W2[(size_t)k * OUT_DIM + j];
        gC[j] = s;
    }
}

// ---------------- SGEMM: Ch[M,N] = A @ B, fp16 output ----------------
template<int BM, int BN, int BK, int TM, int TN>
__global__ void sgemm_h(int M, int N, int K,
                        const float* __restrict__ A,
                        const float* __restrict__ B,
                        __half* __restrict__ Ch)
{
    constexpr int THREADS = (BM / TM) * (BN / TN);
    __shared__ float As[BK][BM];
    __shared__ float Bs[BK][BN];

    const int tid = threadIdx.x;
    const int tc  = tid % (BN / TN);
    const int tr  = tid / (BN / TN);
    const int rowBase = blockIdx.x * BM;
    const int colBase = blockIdx.y * BN;

    float acc[TM][TN];
#pragma unroll
    for (int i = 0; i < TM; i++)
#pragma unroll
        for (int j = 0; j < TN; j++) acc[i][j] = 0.0f;

    constexpr int A_VECS = BM * BK / (THREADS * 4);
    constexpr int B_VECS = BK * BN / (THREADS * 4);

    for (int k0 = 0; k0 < K; k0 += BK) {
#pragma unroll
        for (int i = 0; i < A_VECS; i++) {
            int lin = (tid + i * THREADS) * 4;
            int r = lin / BK, c = lin % BK;
            int grow = rowBase + r;
            float4 v = make_float4(0.f, 0.f, 0.f, 0.f);
            if (grow < M)
                v = *reinterpret_cast<const float4*>(A + (size_t)grow * K + k0 + c);
            As[c + 0][r] = v.x;
            As[c + 1][r] = v.y;
            As[c + 2][r] = v.z;
            As[c + 3][r] = v.w;
        }
#pragma unroll
        for (int i = 0; i < B_VECS; i++) {
            int lin = (tid + i * THREADS) * 4;
            int r = lin / BN, c = lin % BN;
            *reinterpret_cast<float4*>(&Bs[r][c]) =
                *reinterpret_cast<const float4*>(B + (size_t)(k0 + r) * N + colBase + c);
        }
        __syncthreads();

#pragma unroll
        for (int k = 0; k < BK; k++) {
            float ra[TM], rb[TN];
#pragma unroll
            for (int i = 0; i < TM; i++) ra[i] = As[k][tr * TM + i];
#pragma unroll
            for (int j = 0; j < TN; j++) rb[j] = Bs[k][tc * TN + j];
#pragma unroll
            for (int i = 0; i < TM; i++)
#pragma unroll
                for (int j = 0; j < TN; j++) acc[i][j] += ra[i] * rb[j];
        }
        __syncthreads();
    }

#pragma unroll
    for (int i = 0; i < TM; i++) {
        int grow = rowBase + tr * TM + i;
        if (grow >= M) continue;
#pragma unroll
        for (int j = 0; j < TN; j += 2) {
            __half2 h = __floats2half2_rn(acc[i][j], acc[i][j + 1]);
            *reinterpret_cast<__half2*>(Ch + (size_t)grow * N + colBase + tc * TN + j) = h;
        }
    }
}

// ------------- CSR gather prop, DIM=64, fp16 x, fp32 accumulate -------------
// out[n,:] = wscale*sum_e w_e*x[src_e,:] + ascale*addv[n,:] + bscale*bias[:]
// One warp per node; lane l owns half2 pair {2l, 2l+1}.
template<bool HALF_OUT>
__global__ void gather64h(const __half2* __restrict__ x,
                          void* __restrict__ outv,
                          const __half2* __restrict__ addv,  // may be null
                          const float* __restrict__ bias,    // fp32[64], may be null
                          int N, float wscale, float ascale, float bscale)
{
    int warp = (blockIdx.x * blockDim.x + threadIdx.x) >> 5;
    int lane = threadIdx.x & 31;
    if (warp >= N) return;

    int e   = gRowPtr[warp];
    int end = gRowPtr[warp + 1];

    float ax = 0.f, ay = 0.f;

    for (; e + 3 < end; e += 4) {
        int2 s0 = __ldg(&gCsr[e]);
        int2 s1 = __ldg(&gCsr[e + 1]);
        int2 s2 = __ldg(&gCsr[e + 2]);
        int2 s3 = __ldg(&gCsr[e + 3]);
        float2 f0 = __half22float2(__ldg(x + (size_t)s0.x * 32 + lane));
        float2 f1 = __half22float2(__ldg(x + (size_t)s1.x * 32 + lane));
        float2 f2 = __half22float2(__ldg(x + (size_t)s2.x * 32 + lane));
        float2 f3 = __half22float2(__ldg(x + (size_t)s3.x * 32 + lane));
        float w0 = __int_as_float(s0.y);
        float w1 = __int_as_float(s1.y);
        float w2 = __int_as_float(s2.y);
        float w3 = __int_as_float(s3.y);
        ax = fmaf(w0, f0.x, ax); ay = fmaf(w0, f0.y, ay);
        ax = fmaf(w1, f1.x, ax); ay = fmaf(w1, f1.y, ay);
        ax = fmaf(w2, f2.x, ax); ay = fmaf(w2, f2.y, ay);
        ax = fmaf(w3, f3.x, ax); ay = fmaf(w3, f3.y, ay);
    }
    for (; e < end; e++) {
        int2 s0 = __ldg(&gCsr[e]);
        float2 f0 = __half22float2(__ldg(x + (size_t)s0.x * 32 + lane));
        float w0 = __int_as_float(s0.y);
        ax = fmaf(w0, f0.x, ax); ay = fmaf(w0, f0.y, ay);
    }

    float rx = wscale * ax, ry = wscale * ay;
    if (addv) {
        float2 a = __half22float2(__ldg(addv + (size_t)warp * 32 + lane));
        rx = fmaf(ascale, a.x, rx);
        ry = fmaf(ascale, a.y, ry);
    }
    if (bias) {
        float2 b = reinterpret_cast<const float2*>(bias)[lane];
        rx = fmaf(bscale, b.x, rx);
        ry = fmaf(bscale, b.y, ry);
    }
    if (HALF_OUT) {
        reinterpret_cast<__half2*>(outv)[(size_t)warp * 32 + lane] = __floats2half2_rn(rx, ry);
    } else {
        reinterpret_cast<float2*>(outv)[(size_t)warp * 32 + lane] = make_float2(rx, ry);
    }
}

__global__ void fill_tail(float* __restrict__ out, int start, int total)
{
    int i = start + blockIdx.x * blockDim.x + threadIdx.x;
    if (i < total) out[i] = 10.0f;
}

extern "C" void kernel_launch(void* const* d_in, const int* in_sizes, int n_in,
                              void* d_out, int out_size)
{
    const float* features = (const float*)d_in[0];
    const void*  ei       = d_in[1];
    const float* ew       = (const float*)d_in[2];
    const float* W1       = (const float*)d_in[3];
    const float* b1       = (const float*)d_in[4];
    const float* W2       = (const float*)d_in[5];
    const float* b2       = (const float*)d_in[6];
    float*       out      = (float*)d_out;

    const int N = in_sizes[0] / IN_DIM;
    const int E = in_sizes[2];

    __half *X0, *P, *H, *A, *B;
    float  *Wc, *C;
    cudaGetSymbolAddress((void**)&X0, gX0);
    cudaGetSymbolAddress((void**)&P,  gP);
    cudaGetSymbolAddress((void**)&H,  gH);
    cudaGetSymbolAddress((void**)&A,  gA);
    cudaGetSymbolAddress((void**)&B,  gB);
    cudaGetSymbolAddress((void**)&Wc, gWc);
    cudaGetSymbolAddress((void**)&C,  gC);
    int* countPtr;
    cudaGetSymbolAddress((void**)&countPtr, gCount);

    // lazily-created side stream + events (host objects only; created on the
    // non-captured correctness call, reused identically during capture)
    static cudaStream_t sCsr = nullptr;
    static cudaEvent_t  evFork = nullptr, evCsr = nullptr;
    if (!sCsr) {
        cudaStreamCreateWithFlags(&sCsr, cudaStreamNonBlocking);
        cudaEventCreateWithFlags(&evFork, cudaEventDisableTiming);
        cudaEventCreateWithFlags(&evCsr,  cudaEventDisableTiming);
    }

    // ---- fork: CSR build on side stream ----
    cudaEventRecord(evFork, 0);
    cudaStreamWaitEvent(sCsr, evFork, 0);
    detect_idx_dtype<<<1, 1, 0, sCsr>>>(ei, N);
    cudaMemsetAsync(countPtr, 0, (size_t)N * sizeof(int), sCsr);
    hist_dst<<<(E + 255) / 256, 256, 0, sCsr>>>(ei, E);
    scan_rowptr<<<1, 1024, 0, sCsr>>>(N, E);
    fill_csr<<<((E + 1) / 2 + 255) / 256, 256, 0, sCsr>>>(ei, ew, E);
    cudaEventRecord(evCsr, sCsr);

    // ---- main stream: combined weights + GEMM (independent of CSR) ----
    {
        int tot = IN_DIM * OUT_DIM + OUT_DIM;
        combine_weights<<<(tot + 255) / 256, 256>>>(W1, b1, W2);
    }
    {
        dim3 grid((N + 127) / 128, 1);
        sgemm_h<128, 64, 16, 8, 4><<<grid, 256>>>(N, OUT_DIM, IN_DIM, features, Wc, X0);
    }

    // ---- join ----
    cudaStreamWaitEvent(0, evCsr, 0);

    const int gthreads = 256;
    const int wpb = gthreads / 32;
    const int gblocks = (N + wpb - 1) / wpb;
    const float inv = 1.0f / PSCALE;   // 0.25

    // Ps = (prop(X0) + c)/4            [stored scale 4]
    gather64h<true><<<gblocks, gthreads>>>((const __half2*)X0, P, nullptr, C,
                                           N, inv, 0.0f, inv);
    // Hs = (prop(4*Ps) + b2)/16 = 0.25*prop(Ps) + b2/16   [stored scale 16]
    gather64h<true><<<gblocks, gthreads>>>((const __half2*)P, H, nullptr, b2,
                                           N, inv, 0.0f, inv * inv);

    // ---- APPNP with scale tracking: y_{k+1} = (0.9/4)*prop(y_k) + (0.1/4^{k+1})*Hs ----
    const __half* xcur = H;
    float hscale = ALPHA_F;            // 0.1 / 4^{k+1} built up in loop
    for (int k = 0; k < K_STEPS; k++) {
        if (k == K_STEPS - 1) {
            // x_10 = 0.9*prop(y_9)*16*4^9 + 0.1*16*Hs, fp32 output
            const float wfin = (1.0f - ALPHA_F) * 16.0f * 262144.0f;  // 0.9*16*4^9
            const float afin = ALPHA_F * 16.0f;                        // 1.6
            gather64h<false><<<gblocks, gthreads>>>((const __half2*)xcur, out,
                                                    (const __half2*)H, nullptr,
                                                    N, wfin, afin, 0.0f);
        } else {
            hscale *= inv;             // 0.1 / 4^{k+1}
            __half* xnext = (k & 1) ? B : A;
            gather64h<true><<<gblocks, gthreads>>>((const __half2*)xcur, xnext,
                                                   (const __half2*)H, nullptr,
                                                   N, (1.0f - ALPHA_F) * inv, hscale, 0.0f);
            xcur = xnext;
        }
    }

    // tail (reference returns (x, 10); fill any extra outputs with 10)
    int tail = out_size - N * OUT_DIM;
    if (tail > 0)
        fill_tail<<<(tail + 255) / 256, 256>>>(out, N * OUT_DIM, out_size);
}